// round 5
// baseline (speedup 1.0000x reference)
#include <cuda_runtime.h>
#include <cstdint>

typedef unsigned int u32;
typedef unsigned long long u64;

#define NPG   64
#define IN_F  128
#define OUT_F 128
#define XS_STRIDE 140   // words/row; 140 % 32 == 12 -> LDS.64 pattern conflict-free

#define CVT_TF32(d, s) asm("cvt.rna.tf32.f32 %0, %1;" : "=r"(d) : "f"(s))

__device__ __forceinline__ void mma_tf32(float* c,
                                         u32 a0, u32 a1, u32 a2, u32 a3,
                                         u32 b0, u32 b1)
{
    asm volatile(
        "mma.sync.aligned.m16n8k8.row.col.f32.tf32.tf32.f32 "
        "{%0,%1,%2,%3}, {%4,%5,%6,%7}, {%8,%9}, {%0,%1,%2,%3};"
        : "+f"(c[0]), "+f"(c[1]), "+f"(c[2]), "+f"(c[3])
        : "r"(a0), "r"(a1), "r"(a2), "r"(a3), "r"(b0), "r"(b1));
}

__global__ void __launch_bounds__(512, 2)
mhl_mma_kernel(const float* __restrict__ x,
               const int*   __restrict__ head,
               const float* __restrict__ kern,
               const float* __restrict__ bias,
               float*       __restrict__ out)
{
    __shared__ u32 Xs[NPG * XS_STRIDE];   // 35840 B, tf32 X tile, columns permuted per 8-group

    const int tid  = threadIdx.x;
    const int wid  = tid >> 5;            // 16 warps: 2m x 8n
    const int lane = tid & 31;
    const int gid  = lane >> 2;
    const int tig  = lane & 3;
    const int g    = blockIdx.x;
    const int h    = __ldg(head + g);

    const int mw = wid >> 3;              // 0..1 -> m0 = mw*32
    const int nw = wid & 7;               // 0..7 -> n0 = nw*16
    const int m0 = mw * 32;
    const int n0 = nw * 16;

    // ---- stage X -> smem tf32, column-permuted: col' = (c>>3)*8 + (c&3)*2 + ((c>>2)&1)
    {
        const float4* Xg = (const float4*)(x + (size_t)g * NPG * IN_F);
        #pragma unroll
        for (int it = 0; it < 4; it++) {
            const int idx  = tid + it * 512;          // 2048 float4 chunks
            const int node = idx >> 5;
            const int c4   = idx & 31;
            float4 v = Xg[idx];
            u32 r0, r1, r2, r3;
            CVT_TF32(r0, v.x); CVT_TF32(r1, v.y);
            CVT_TF32(r2, v.z); CVT_TF32(r3, v.w);
            u32* dst = &Xs[node * XS_STRIDE + (c4 >> 1) * 8 + (c4 & 1)];
            dst[0] = r0; dst[2] = r1; dst[4] = r2; dst[6] = r3;
        }
    }
    __syncthreads();

    float acc[2][2][4];
    #pragma unroll
    for (int i = 0; i < 2; i++)
        #pragma unroll
        for (int j = 0; j < 2; j++)
            #pragma unroll
            for (int r = 0; r < 4; r++)
                acc[i][j][r] = 0.0f;

    // W element (k, n) at kern[h*16384 + k*128 + n]; this warp's n = n0 + 8j + gid
    const float* pW = kern + (size_t)h * IN_F * OUT_F + tig * OUT_F + n0 + gid;
    const u32*   pX = Xs + gid * XS_STRIDE + tig * 2;

    // prefetch step 0 W
    float wn[2][2];
    #pragma unroll
    for (int j = 0; j < 2; j++) {
        wn[j][0] = __ldg(pW + j * 8);                 // k = tig
        wn[j][1] = __ldg(pW + 4 * OUT_F + j * 8);     // k = tig + 4
    }

    #pragma unroll
    for (int s = 0; s < 16; s++) {
        u32 b0[2], b1[2];
        #pragma unroll
        for (int j = 0; j < 2; j++) {
            CVT_TF32(b0[j], wn[j][0]);
            CVT_TF32(b1[j], wn[j][1]);
        }
        if (s < 15) {
            const float* pWn = pW + (s + 1) * 8 * OUT_F;
            #pragma unroll
            for (int j = 0; j < 2; j++) {
                wn[j][0] = __ldg(pWn + j * 8);
                wn[j][1] = __ldg(pWn + 4 * OUT_F + j * 8);
            }
        }
        #pragma unroll
        for (int i = 0; i < 2; i++) {
            // rows: m0 + i*16 + gid (+8); cols (permuted): s*8 + 2*tig, +1  -> one LDS.64 each
            const u32* pa = pX + (m0 + i * 16) * XS_STRIDE + s * 8;
            u64 w0 = *(const u64*)pa;                         // {a0, a2}
            u64 w1 = *(const u64*)(pa + 8 * XS_STRIDE);       // {a1, a3}
            u32 a0 = (u32)w0, a2 = (u32)(w0 >> 32);
            u32 a1 = (u32)w1, a3 = (u32)(w1 >> 32);
            mma_tf32(acc[i][0], a0, a1, a2, a3, b0[0], b1[0]);
            mma_tf32(acc[i][1], a0, a1, a2, a3, b0[1], b1[1]);
        }
    }

    // ---- epilogue: bias + float2 stores ----
    float bb[2][2];
    #pragma unroll
    for (int j = 0; j < 2; j++) {
        const int col = n0 + 8 * j + 2 * tig;
        bb[j][0] = __ldg(bias + (size_t)h * OUT_F + col);
        bb[j][1] = __ldg(bias + (size_t)h * OUT_F + col + 1);
    }

    #pragma unroll
    for (int i = 0; i < 2; i++) {
        const int node0 = g * NPG + m0 + 16 * i + gid;
        #pragma unroll
        for (int j = 0; j < 2; j++) {
            const int col = n0 + 8 * j + 2 * tig;
            float2 v0 = make_float2(acc[i][j][0] + bb[j][0], acc[i][j][1] + bb[j][1]);
            float2 v1 = make_float2(acc[i][j][2] + bb[j][0], acc[i][j][3] + bb[j][1]);
            *(float2*)&out[(size_t)node0 * OUT_F + col]       = v0;
            *(float2*)&out[(size_t)(node0 + 8) * OUT_F + col] = v1;
        }
    }
}

extern "C" void kernel_launch(void* const* d_in, const int* in_sizes, int n_in,
                              void* d_out, int out_size)
{
    const float* inputs = (const float*)d_in[0];
    const int*   head   = (const int*)d_in[2];
    const float* kern   = (const float*)d_in[3];
    const float* bias   = (const float*)d_in[4];
    float*       out    = (float*)d_out;
    const int n_graphs  = in_sizes[2];   // 256

    mhl_mma_kernel<<<n_graphs, 512>>>(inputs, head, kern, bias, out);
}

// round 6
// speedup vs baseline: 1.1404x; 1.1404x over previous
#include <cuda_runtime.h>
#include <cstdint>

typedef unsigned int u32;
typedef unsigned long long u64;

#define NPG   64
#define IN_F  128
#define OUT_F 128
#define M_CTA 32        // nodes per CTA (graph split in 2)
#define XS_STRIDE 136   // words/row; 136 % 32 == 8 -> LDS.64 conflict-free per 16-lane phase

#define CVT_TF32(d, s) asm("cvt.rna.tf32.f32 %0, %1;" : "=r"(d) : "f"(s))

__device__ __forceinline__ void mma_tf32(float* c,
                                         u32 a0, u32 a1, u32 a2, u32 a3,
                                         u32 b0, u32 b1)
{
    asm volatile(
        "mma.sync.aligned.m16n8k8.row.col.f32.tf32.tf32.f32 "
        "{%0,%1,%2,%3}, {%4,%5,%6,%7}, {%8,%9}, {%0,%1,%2,%3};"
        : "+f"(c[0]), "+f"(c[1]), "+f"(c[2]), "+f"(c[3])
        : "r"(a0), "r"(a1), "r"(a2), "r"(a3), "r"(b0), "r"(b1));
}

__global__ void __launch_bounds__(256)
mhl_mma_kernel(const float* __restrict__ x,
               const int*   __restrict__ head,
               const float* __restrict__ kern,
               const float* __restrict__ bias,
               float*       __restrict__ out)
{
    __shared__ u32 Xs[M_CTA * XS_STRIDE];   // 17408 B, tf32 X half-tile, cols permuted per 8-group

    const int tid  = threadIdx.x;
    const int wid  = tid >> 5;              // 8 warps, each owns n-slice of 16
    const int lane = tid & 31;
    const int gid  = lane >> 2;
    const int tig  = lane & 3;
    const int g    = blockIdx.x >> 1;       // graph
    const int mh   = blockIdx.x & 1;        // which 32-node half
    const int h    = __ldg(head + g);
    const int n0   = wid * 16;

    // ---- stage X[32][128] -> smem tf32, column pair-permuted:
    //      within each 8-col group, col' = (c&3)*2 + ((c>>2)&1)  (puts k and k+4 adjacent)
    {
        const float4* Xg = (const float4*)(x + ((size_t)g * NPG + mh * M_CTA) * IN_F);
        #pragma unroll
        for (int it = 0; it < 4; it++) {
            const int idx  = tid + it * 256;          // 1024 float4 chunks
            const int node = idx >> 5;
            const int c4   = idx & 31;
            float4 v = Xg[idx];
            u32 r0, r1, r2, r3;
            CVT_TF32(r0, v.x); CVT_TF32(r1, v.y);
            CVT_TF32(r2, v.z); CVT_TF32(r3, v.w);
            u32* dst = &Xs[node * XS_STRIDE + (c4 >> 1) * 8 + (c4 & 1)];
            dst[0] = r0; dst[2] = r1; dst[4] = r2; dst[6] = r3;
        }
    }
    __syncthreads();

    float acc[2][2][4];
    #pragma unroll
    for (int i = 0; i < 2; i++)
        #pragma unroll
        for (int j = 0; j < 2; j++)
            #pragma unroll
            for (int r = 0; r < 4; r++)
                acc[i][j][r] = 0.0f;

    // W element (k, n) at kern[h*16384 + k*128 + n]; this warp's n = n0 + 8j + gid
    const float* pW = kern + (size_t)h * IN_F * OUT_F + tig * OUT_F + n0 + gid;
    const u32*   pX = Xs + gid * XS_STRIDE + tig * 2;

    // prefetch step 0 W
    float wn[2][2];
    #pragma unroll
    for (int j = 0; j < 2; j++) {
        wn[j][0] = __ldg(pW + j * 8);                 // k = tig
        wn[j][1] = __ldg(pW + 4 * OUT_F + j * 8);     // k = tig + 4
    }

    #pragma unroll
    for (int s = 0; s < 16; s++) {
        u32 b0[2], b1[2];
        #pragma unroll
        for (int j = 0; j < 2; j++) {
            CVT_TF32(b0[j], wn[j][0]);
            CVT_TF32(b1[j], wn[j][1]);
        }
        if (s < 15) {
            const float* pWn = pW + (s + 1) * 8 * OUT_F;
            #pragma unroll
            for (int j = 0; j < 2; j++) {
                wn[j][0] = __ldg(pWn + j * 8);
                wn[j][1] = __ldg(pWn + 4 * OUT_F + j * 8);
            }
        }
        #pragma unroll
        for (int i = 0; i < 2; i++) {
            // rows: i*16 + gid (+8); permuted cols: s*8 + 2*tig (,+1) -> one LDS.64 each
            const u32* pa = pX + i * 16 * XS_STRIDE + s * 8;
            u64 w0 = *(const u64*)pa;                         // {a0, a2}
            u64 w1 = *(const u64*)(pa + 8 * XS_STRIDE);       // {a1, a3}
            u32 a0 = (u32)w0, a2 = (u32)(w0 >> 32);
            u32 a1 = (u32)w1, a3 = (u32)(w1 >> 32);
            mma_tf32(acc[i][0], a0, a1, a2, a3, b0[0], b1[0]);
            mma_tf32(acc[i][1], a0, a1, a2, a3, b0[1], b1[1]);
        }
    }

    // ---- epilogue: bias + coalesced float2 stores ----
    float bb[2][2];
    #pragma unroll
    for (int j = 0; j < 2; j++) {
        const int col = n0 + 8 * j + 2 * tig;
        bb[j][0] = __ldg(bias + (size_t)h * OUT_F + col);
        bb[j][1] = __ldg(bias + (size_t)h * OUT_F + col + 1);
    }

    #pragma unroll
    for (int i = 0; i < 2; i++) {
        const int node0 = g * NPG + mh * M_CTA + 16 * i + gid;
        #pragma unroll
        for (int j = 0; j < 2; j++) {
            const int col = n0 + 8 * j + 2 * tig;
            float2 v0 = make_float2(acc[i][j][0] + bb[j][0], acc[i][j][1] + bb[j][1]);
            float2 v1 = make_float2(acc[i][j][2] + bb[j][0], acc[i][j][3] + bb[j][1]);
            *(float2*)&out[(size_t)node0 * OUT_F + col]       = v0;
            *(float2*)&out[(size_t)(node0 + 8) * OUT_F + col] = v1;
        }
    }
}

extern "C" void kernel_launch(void* const* d_in, const int* in_sizes, int n_in,
                              void* d_out, int out_size)
{
    const float* inputs = (const float*)d_in[0];
    const int*   head   = (const int*)d_in[2];
    const float* kern   = (const float*)d_in[3];
    const float* bias   = (const float*)d_in[4];
    float*       out    = (float*)d_out;
    const int n_graphs  = in_sizes[2];   // 256

    mhl_mma_kernel<<<n_graphs * 2, 256>>>(inputs, head, kern, bias, out);
}

// round 7
// speedup vs baseline: 1.3401x; 1.1751x over previous
#include <cuda_runtime.h>
#include <cstdint>

typedef unsigned int u32;

#define NPG   64
#define IN_F  128
#define OUT_F 128
#define XS_STRIDE 132   // A-LDS banks: gid*4 + tig  -> conflict-free
#define WS_STRIDE 136   // B-LDS banks: tig*8 + gid  -> conflict-free

#define CVT_TF32(d, s) asm("cvt.rna.tf32.f32 %0, %1;" : "=r"(d) : "f"(s))

__device__ __forceinline__ void mma_tf32(float* c,
                                         u32 a0, u32 a1, u32 a2, u32 a3,
                                         u32 b0, u32 b1)
{
    asm volatile(
        "mma.sync.aligned.m16n8k8.row.col.f32.tf32.tf32.f32 "
        "{%0,%1,%2,%3}, {%4,%5,%6,%7}, {%8,%9}, {%0,%1,%2,%3};"
        : "+f"(c[0]), "+f"(c[1]), "+f"(c[2]), "+f"(c[3])
        : "r"(a0), "r"(a1), "r"(a2), "r"(a3), "r"(b0), "r"(b1));
}

// dynamic smem: Ws [128][136] then Xs [64][132]
#define WS_WORDS (IN_F * WS_STRIDE)          // 17408
#define XS_WORDS (NPG * XS_STRIDE)           // 8448
#define SMEM_BYTES ((WS_WORDS + XS_WORDS) * 4)   // 103424

__global__ void __launch_bounds__(256, 2)
mhl_mma_kernel(const float* __restrict__ x,
               const int*   __restrict__ head,
               const float* __restrict__ kern,
               const float* __restrict__ bias,
               float*       __restrict__ out)
{
    extern __shared__ u32 smem[];
    u32* Ws = smem;              // tf32 W[k][n], stride 136
    u32* Xs = smem + WS_WORDS;   // tf32 X[node][k], stride 132

    const int tid  = threadIdx.x;
    const int wid  = tid >> 5;            // 8 warps: 2m x 4n
    const int lane = tid & 31;
    const int gid  = lane >> 2;
    const int tig  = lane & 3;
    const int g    = blockIdx.x;
    const int h    = __ldg(head + g);

    const int m0 = (wid >> 2) * 32;       // 0 or 32
    const int n0 = (wid & 3) * 32;        // 0,32,64,96

    // ---- stage W[h] -> smem tf32 (coalesced LDG.128, row-aligned STS) ----
    {
        const float4* W4 = (const float4*)(kern + (size_t)h * IN_F * OUT_F);
        #pragma unroll
        for (int it = 0; it < 16; it++) {
            const int idx = tid + it * 256;       // 4096 float4
            const int k   = idx >> 5;
            const int c4  = idx & 31;
            float4 v = W4[idx];
            u32 r0, r1, r2, r3;
            CVT_TF32(r0, v.x); CVT_TF32(r1, v.y);
            CVT_TF32(r2, v.z); CVT_TF32(r3, v.w);
            u32* dst = &Ws[k * WS_STRIDE + c4 * 4];
            dst[0] = r0; dst[1] = r1; dst[2] = r2; dst[3] = r3;
        }
    }
    // ---- stage X[g] -> smem tf32 ----
    {
        const float4* X4 = (const float4*)(x + (size_t)g * NPG * IN_F);
        #pragma unroll
        for (int it = 0; it < 8; it++) {
            const int idx  = tid + it * 256;      // 2048 float4
            const int node = idx >> 5;
            const int c4   = idx & 31;
            float4 v = X4[idx];
            u32 r0, r1, r2, r3;
            CVT_TF32(r0, v.x); CVT_TF32(r1, v.y);
            CVT_TF32(r2, v.z); CVT_TF32(r3, v.w);
            u32* dst = &Xs[node * XS_STRIDE + c4 * 4];
            dst[0] = r0; dst[1] = r1; dst[2] = r2; dst[3] = r3;
        }
    }
    __syncthreads();

    float acc[2][4][4];
    #pragma unroll
    for (int i = 0; i < 2; i++)
        #pragma unroll
        for (int j = 0; j < 4; j++)
            #pragma unroll
            for (int r = 0; r < 4; r++)
                acc[i][j][r] = 0.0f;

    const u32* pX = Xs + (m0 + gid) * XS_STRIDE + tig;     // A base
    const u32* pB = Ws + tig * WS_STRIDE + n0 + gid;       // B base (k=tig row)

    #pragma unroll
    for (int s = 0; s < 16; s++) {
        // B fragments: 4 n-tiles x 2 k-halves, conflict-free LDS.32
        u32 b0[4], b1[4];
        const u32* pb = pB + s * 8 * WS_STRIDE;
        #pragma unroll
        for (int j = 0; j < 4; j++) {
            b0[j] = pb[j * 8];
            b1[j] = pb[4 * WS_STRIDE + j * 8];
        }
        // A fragments + MMAs per m-tile
        #pragma unroll
        for (int i = 0; i < 2; i++) {
            const u32* pa = pX + i * 16 * XS_STRIDE + s * 8;
            u32 a0 = pa[0];
            u32 a1 = pa[8 * XS_STRIDE];
            u32 a2 = pa[4];
            u32 a3 = pa[8 * XS_STRIDE + 4];
            #pragma unroll
            for (int j = 0; j < 4; j++)
                mma_tf32(acc[i][j], a0, a1, a2, a3, b0[j], b1[j]);
        }
    }

    // ---- epilogue: bias + coalesced float2 stores ----
    float bb[4][2];
    #pragma unroll
    for (int j = 0; j < 4; j++) {
        const int col = n0 + 8 * j + 2 * tig;
        bb[j][0] = __ldg(bias + (size_t)h * OUT_F + col);
        bb[j][1] = __ldg(bias + (size_t)h * OUT_F + col + 1);
    }

    #pragma unroll
    for (int i = 0; i < 2; i++) {
        const int node0 = g * NPG + m0 + 16 * i + gid;
        #pragma unroll
        for (int j = 0; j < 4; j++) {
            const int col = n0 + 8 * j + 2 * tig;
            float2 v0 = make_float2(acc[i][j][0] + bb[j][0], acc[i][j][1] + bb[j][1]);
            float2 v1 = make_float2(acc[i][j][2] + bb[j][0], acc[i][j][3] + bb[j][1]);
            *(float2*)&out[(size_t)node0 * OUT_F + col]       = v0;
            *(float2*)&out[(size_t)(node0 + 8) * OUT_F + col] = v1;
        }
    }
}

extern "C" void kernel_launch(void* const* d_in, const int* in_sizes, int n_in,
                              void* d_out, int out_size)
{
    const float* inputs = (const float*)d_in[0];
    const int*   head   = (const int*)d_in[2];
    const float* kern   = (const float*)d_in[3];
    const float* bias   = (const float*)d_in[4];
    float*       out    = (float*)d_out;
    const int n_graphs  = in_sizes[2];   // 256

    static bool attr_set = false;
    if (!attr_set) {
        cudaFuncSetAttribute(mhl_mma_kernel, cudaFuncAttributeMaxDynamicSharedMemorySize, SMEM_BYTES);
        attr_set = true;
    }
    mhl_mma_kernel<<<n_graphs, 256, SMEM_BYTES>>>(inputs, head, kern, bias, out);
}